// round 8
// baseline (speedup 1.0000x reference)
#include <cuda_runtime.h>

#define KW 7
#define PAD 3
#define H 480
#define W 640
#define NB 4
#define HW (H * W)
#define TX 32
#define TY 8
#define TILE_W (TX + 2 * PAD)   // 38
#define TILE_H (TY + 2 * PAD)   // 14
// exponent constant: -1/(2*0.1^2) * log2(e) = -50 * log2(e)
#define NEG50_LOG2E (-72.13475204444817f)

typedef unsigned long long u64;

__device__ __forceinline__ u64 pk(float lo, float hi) {
    u64 r; asm("mov.b64 %0, {%1, %2};" : "=l"(r) : "f"(lo), "f"(hi)); return r;
}
__device__ __forceinline__ void upk(float& lo, float& hi, u64 v) {
    asm("mov.b64 {%0, %1}, %2;" : "=f"(lo), "=f"(hi) : "l"(v));
}
__device__ __forceinline__ u64 add2(u64 a, u64 b) {
    u64 r; asm("add.rn.f32x2 %0, %1, %2;" : "=l"(r) : "l"(a), "l"(b)); return r;
}
__device__ __forceinline__ u64 mul2(u64 a, u64 b) {
    u64 r; asm("mul.rn.f32x2 %0, %1, %2;" : "=l"(r) : "l"(a), "l"(b)); return r;
}
__device__ __forceinline__ u64 fma2(u64 a, u64 b, u64 c) {
    u64 r; asm("fma.rn.f32x2 %0, %1, %2, %3;" : "=l"(r) : "l"(a), "l"(b), "l"(c)); return r;
}
__device__ __forceinline__ float ex2(float x) {
    float r; asm("ex2.approx.f32 %0, %1;" : "=f"(r) : "f"(x)); return r;
}

__global__ __launch_bounds__(TX * TY, 8) void bilateral_kernel(
    const float* __restrict__ I,
    const float* __restrict__ g,
    float* __restrict__ out)
{
    // batch-interleaved tile; u64 pairs feed f32x2 ops directly (no pack movs)
    __shared__ ulonglong2 tile[TILE_H][TILE_W];   // 8512 B
    __shared__ float2 lg2s[KW * KW];              // pre-broadcast log2(g) per tap

    const int x0 = blockIdx.x * TX;
    const int y0 = blockIdx.y * TY;
    const int tx = threadIdx.x;
    const int ty = threadIdx.y;
    const int tid = ty * TX + tx;

    if (tid < KW * KW) {
        const float lv = __log2f(__ldg(g + tid * HW));
        lg2s[tid] = make_float2(lv, lv);
    }

    // Halo tile: 4 batch values per pixel, stored interleaved.
    for (int i = tid; i < TILE_H * TILE_W; i += TX * TY) {
        const int ly = i / TILE_W;
        const int lx = i - ly * TILE_W;
        const int gy = y0 + ly - PAD;
        const int gx = x0 + lx - PAD;
        float v0 = 0.f, v1 = 0.f, v2 = 0.f, v3 = 0.f;
        if (gy >= 0 && gy < H && gx >= 0 && gx < W) {
            const int base = gy * W + gx;
            v0 = I[0 * HW + base];
            v1 = I[1 * HW + base];
            v2 = I[2 * HW + base];
            v3 = I[3 * HW + base];
        }
        ulonglong2 u;
        u.x = pk(v0, v1);
        u.y = pk(v2, v3);
        tile[ly][lx] = u;
    }
    __syncthreads();

    const ulonglong2 cc = tile[ty + PAD][tx + PAD];
    float c0, c1, c2, c3;
    upk(c0, c1, cc.x);
    upk(c2, c3, cc.y);
    const u64 nc01 = pk(-c0, -c1);
    const u64 nc23 = pk(-c2, -c3);
    const u64 C2 = pk(NEG50_LOG2E, NEG50_LOG2E);

    u64 num01 = 0ull, num23 = 0ull, den01 = 0ull, den23 = 0ull;

    #pragma unroll
    for (int dy = 0; dy < KW; dy++) {
        #pragma unroll
        for (int dx = 0; dx < KW; dx++) {
            const ulonglong2 s = tile[ty + dy][tx + dx];       // LDS.128 -> u64 pair
            const u64 lgb = *reinterpret_cast<const u64*>(&lg2s[dy * KW + dx]); // LDS.64 bcast

            const u64 d01 = add2(s.x, nc01);
            const u64 d23 = add2(s.y, nc23);
            const u64 q01 = mul2(d01, d01);
            const u64 q23 = mul2(d23, d23);
            const u64 e01 = fma2(C2, q01, lgb);
            const u64 e23 = fma2(C2, q23, lgb);

            float e0, e1, e2, e3;
            upk(e0, e1, e01);
            upk(e2, e3, e23);
            const u64 w01 = pk(ex2(e0), ex2(e1));
            const u64 w23 = pk(ex2(e2), ex2(e3));

            den01 = add2(den01, w01);
            den23 = add2(den23, w23);
            num01 = fma2(w01, s.x, num01);
            num23 = fma2(w23, s.y, num23);
        }
    }

    float n0, n1, n2, n3, de0, de1, de2, de3;
    upk(n0, n1, num01); upk(n2, n3, num23);
    upk(de0, de1, den01); upk(de2, de3, den23);

    const int oidx = (y0 + ty) * W + (x0 + tx);
    out[0 * HW + oidx] = __fdividef(n0, de0);
    out[1 * HW + oidx] = __fdividef(n1, de1);
    out[2 * HW + oidx] = __fdividef(n2, de2);
    out[3 * HW + oidx] = __fdividef(n3, de3);
}

extern "C" void kernel_launch(void* const* d_in, const int* in_sizes, int n_in,
                              void* d_out, int out_size)
{
    const float* I = (const float*)d_in[0];
    const float* g = (const float*)d_in[1];
    float* out = (float*)d_out;

    dim3 block(TX, TY);
    dim3 grid(W / TX, H / TY);   // 20 x 60, exact
    bilateral_kernel<<<grid, block>>>(I, g, out);
}

// round 9
// speedup vs baseline: 1.0097x; 1.0097x over previous
#include <cuda_runtime.h>

#define KW 7
#define PAD 3
#define H 480
#define W 640
#define NB 4
#define HW (H * W)
#define TX 32
#define TY 4                      // thread rows; each thread does 2 output rows
#define BH (TY * 2)               // 8 image rows per block
#define TILE_W (TX + 2 * PAD)     // 38
#define TILE_H (BH + 2 * PAD)     // 14
#define NTHREADS (TX * TY)        // 128
// exponent constant: -1/(2*0.1^2) * log2(e) = -50 * log2(e)
#define NEG50_LOG2E (-72.13475204444817f)

typedef unsigned long long u64;

__device__ __forceinline__ u64 pk(float lo, float hi) {
    u64 r; asm("mov.b64 %0, {%1, %2};" : "=l"(r) : "f"(lo), "f"(hi)); return r;
}
__device__ __forceinline__ void upk(float& lo, float& hi, u64 v) {
    asm("mov.b64 {%0, %1}, %2;" : "=f"(lo), "=f"(hi) : "l"(v));
}
__device__ __forceinline__ u64 add2(u64 a, u64 b) {
    u64 r; asm("add.rn.f32x2 %0, %1, %2;" : "=l"(r) : "l"(a), "l"(b)); return r;
}
__device__ __forceinline__ u64 mul2(u64 a, u64 b) {
    u64 r; asm("mul.rn.f32x2 %0, %1, %2;" : "=l"(r) : "l"(a), "l"(b)); return r;
}
__device__ __forceinline__ u64 fma2(u64 a, u64 b, u64 c) {
    u64 r; asm("fma.rn.f32x2 %0, %1, %2, %3;" : "=l"(r) : "l"(a), "l"(b), "l"(c)); return r;
}
__device__ __forceinline__ float ex2(float x) {
    float r; asm("ex2.approx.f32 %0, %1;" : "=f"(r) : "f"(x)); return r;
}

struct Acc { u64 num01, num23, den01, den23; };

__device__ __forceinline__ void tap(Acc& a, const ulonglong2 s, const u64 lgb,
                                    const u64 nc01, const u64 nc23, const u64 C2)
{
    const u64 d01 = add2(s.x, nc01);
    const u64 d23 = add2(s.y, nc23);
    const u64 q01 = mul2(d01, d01);
    const u64 q23 = mul2(d23, d23);
    const u64 e01 = fma2(C2, q01, lgb);
    const u64 e23 = fma2(C2, q23, lgb);
    float e0, e1, e2, e3;
    upk(e0, e1, e01);
    upk(e2, e3, e23);
    const u64 w01 = pk(ex2(e0), ex2(e1));
    const u64 w23 = pk(ex2(e2), ex2(e3));
    a.den01 = add2(a.den01, w01);
    a.den23 = add2(a.den23, w23);
    a.num01 = fma2(w01, s.x, a.num01);
    a.num23 = fma2(w23, s.y, a.num23);
}

__global__ __launch_bounds__(NTHREADS) void bilateral_kernel(
    const float* __restrict__ I,
    const float* __restrict__ g,
    float* __restrict__ out)
{
    __shared__ ulonglong2 tile[TILE_H][TILE_W];   // batch-interleaved, 8512 B
    __shared__ float2 lg2s[KW * KW];              // pre-broadcast log2(g)

    const int x0 = blockIdx.x * TX;
    const int y0 = blockIdx.y * BH;
    const int tx = threadIdx.x;
    const int ty = threadIdx.y;
    const int tid = ty * TX + tx;

    if (tid < KW * KW) {
        const float lv = __log2f(__ldg(g + tid * HW));
        lg2s[tid] = make_float2(lv, lv);
    }

    // Halo tile load (zero pad outside image), batch-interleaved u64 pairs.
    for (int i = tid; i < TILE_H * TILE_W; i += NTHREADS) {
        const int ly = i / TILE_W;
        const int lx = i - ly * TILE_W;
        const int gy = y0 + ly - PAD;
        const int gx = x0 + lx - PAD;
        float v0 = 0.f, v1 = 0.f, v2 = 0.f, v3 = 0.f;
        if (gy >= 0 && gy < H && gx >= 0 && gx < W) {
            const int base = gy * W + gx;
            v0 = I[0 * HW + base];
            v1 = I[1 * HW + base];
            v2 = I[2 * HW + base];
            v3 = I[3 * HW + base];
        }
        ulonglong2 u;
        u.x = pk(v0, v1);
        u.y = pk(v2, v3);
        tile[ly][lx] = u;
    }
    __syncthreads();

    const int tr = 2 * ty;   // tile-row base of pixel0's window

    // Centers for the two output pixels of this thread.
    const ulonglong2 cA = tile[tr + PAD][tx + PAD];
    const ulonglong2 cB = tile[tr + PAD + 1][tx + PAD];
    float a0, a1, a2, a3, b0, b1, b2, b3;
    upk(a0, a1, cA.x); upk(a2, a3, cA.y);
    upk(b0, b1, cB.x); upk(b2, b3, cB.y);
    const u64 ncA01 = pk(-a0, -a1), ncA23 = pk(-a2, -a3);
    const u64 ncB01 = pk(-b0, -b1), ncB23 = pk(-b2, -b3);
    const u64 C2 = pk(NEG50_LOG2E, NEG50_LOG2E);

    Acc accA = {0ull, 0ull, 0ull, 0ull};
    Acc accB = {0ull, 0ull, 0ull, 0ull};

    // Union of both pixels' windows: 8 tile rows. One LDS.128 feeds both.
    #pragma unroll
    for (int dy = 0; dy < KW + 1; dy++) {
        #pragma unroll
        for (int dx = 0; dx < KW; dx++) {
            const ulonglong2 s = tile[tr + dy][tx + dx];
            if (dy < KW) {     // pixel A: tap row dy
                const u64 lgb = *reinterpret_cast<const u64*>(&lg2s[dy * KW + dx]);
                tap(accA, s, lgb, ncA01, ncA23, C2);
            }
            if (dy >= 1) {     // pixel B: tap row dy-1
                const u64 lgb = *reinterpret_cast<const u64*>(&lg2s[(dy - 1) * KW + dx]);
                tap(accB, s, lgb, ncB01, ncB23, C2);
            }
        }
    }

    float n0, n1, n2, n3, d0, d1, d2, d3;
    const int yA = y0 + tr;
    const int oA = yA * W + x0 + tx;
    upk(n0, n1, accA.num01); upk(n2, n3, accA.num23);
    upk(d0, d1, accA.den01); upk(d2, d3, accA.den23);
    out[0 * HW + oA] = __fdividef(n0, d0);
    out[1 * HW + oA] = __fdividef(n1, d1);
    out[2 * HW + oA] = __fdividef(n2, d2);
    out[3 * HW + oA] = __fdividef(n3, d3);

    const int oB = oA + W;
    upk(n0, n1, accB.num01); upk(n2, n3, accB.num23);
    upk(d0, d1, accB.den01); upk(d2, d3, accB.den23);
    out[0 * HW + oB] = __fdividef(n0, d0);
    out[1 * HW + oB] = __fdividef(n1, d1);
    out[2 * HW + oB] = __fdividef(n2, d2);
    out[3 * HW + oB] = __fdividef(n3, d3);
}

extern "C" void kernel_launch(void* const* d_in, const int* in_sizes, int n_in,
                              void* d_out, int out_size)
{
    const float* I = (const float*)d_in[0];
    const float* g = (const float*)d_in[1];
    float* out = (float*)d_out;

    dim3 block(TX, TY);
    dim3 grid(W / TX, H / BH);   // 20 x 60 = 1200 blocks, 4 warps each -> single wave
    bilateral_kernel<<<grid, block>>>(I, g, out);
}